// round 3
// baseline (speedup 1.0000x reference)
#include <cuda_runtime.h>
#include <cuda_bf16.h>
#include <cstddef>

// ---------------------------------------------------------------------------
// Problem constants
// ---------------------------------------------------------------------------
#define Bn   8
#define Cc   512
#define Nn   2304      // 48*48
#define C1n  256
#define C2n  256
#define CGn  128
#define Gg   4
#define OUTC 512
#define EPSf 1e-5f
#define SCALEf (1.0f/16.0f)   // C1^-0.5 = 256^-0.5

// ---------------------------------------------------------------------------
// Scratch (device globals: allocation-free per harness rules)
// ---------------------------------------------------------------------------
// PROJ[t][g][b][256][N], t in {0:theta, 1:phi, 2:g}
__device__ float g_PROJ[(size_t)3 * Gg * Bn * C1n * Nn];     // 226 MB
// A[b][N][N] : attention probs for ONE stage at a time (stages looped)
__device__ float g_A[(size_t)Bn * Nn * Nn];                  // 170 MB
// Y[g][b][256][N]
__device__ float g_Y[(size_t)Gg * Bn * C2n * Nn];            // 75.5 MB
// PR[b][512][n] : W-conv outputs laid out in final concat channel order
__device__ float g_PR[(size_t)Bn * (Gg * CGn) * Nn];         // 37.7 MB
// BN statistics + folded params
__device__ float g_mean1[512], g_var1[512];
__device__ float g_mean2[512], g_var2[512];
__device__ float g_tc[512];        // BN fold: additive term per pr channel
__device__ float g_ws[1024];       // per-k column scale for bottleneck GEMM
__device__ float g_const[512];     // folded bias for bottleneck GEMM

// ---------------------------------------------------------------------------
// Generic tiled SGEMM body: C[o, n] = sum_k W[o,k] * X[k,n] + bias[o]
// BM=BN=64, BK=16, 256 threads, 4x4 per thread.
// W row-major with leading dim K, X row-major with leading dim Nn.
// ---------------------------------------------------------------------------
__device__ __forceinline__ void gemm_body(const float* __restrict__ W,
                                          const float* __restrict__ X,
                                          const float* __restrict__ bias,
                                          float* __restrict__ Cp, int K)
{
    __shared__ float Ws[16][68];   // [k][o], padded
    __shared__ float Xs[16][64];   // [k][n]
    const int t  = threadIdx.x;
    const int n0 = blockIdx.x * 64;
    const int o0 = blockIdx.y * 64;
    const int tx = t & 15, ty = t >> 4;
    const int wrow = t >> 2, wc4 = t & 3;    // W tile loads
    const int xrow = t >> 4, xc4 = t & 15;   // X tile loads

    float acc[4][4] = {};
    for (int k0 = 0; k0 < K; k0 += 16) {
        float4 wv = *(const float4*)&W[(size_t)(o0 + wrow) * K + k0 + wc4 * 4];
        float4 xv = *(const float4*)&X[(size_t)(k0 + xrow) * Nn + n0 + xc4 * 4];
        __syncthreads();
        Ws[wc4 * 4 + 0][wrow] = wv.x;
        Ws[wc4 * 4 + 1][wrow] = wv.y;
        Ws[wc4 * 4 + 2][wrow] = wv.z;
        Ws[wc4 * 4 + 3][wrow] = wv.w;
        *(float4*)&Xs[xrow][xc4 * 4] = xv;
        __syncthreads();
#pragma unroll
        for (int kk = 0; kk < 16; kk++) {
            float4 a4 = *(const float4*)&Ws[kk][ty * 4];
            float4 b4 = *(const float4*)&Xs[kk][tx * 4];
            float a[4] = {a4.x, a4.y, a4.z, a4.w};
            float b[4] = {b4.x, b4.y, b4.z, b4.w};
#pragma unroll
            for (int j = 0; j < 4; j++)
#pragma unroll
                for (int i = 0; i < 4; i++)
                    acc[j][i] += a[j] * b[i];
        }
    }
#pragma unroll
    for (int j = 0; j < 4; j++) {
        float bb = bias ? bias[o0 + ty * 4 + j] : 0.0f;
#pragma unroll
        for (int i = 0; i < 4; i++)
            Cp[(size_t)(o0 + ty * 4 + j) * Nn + n0 + tx * 4 + i] = acc[j][i] + bb;
    }
}

// ---------------------------------------------------------------------------
// K1: projections.  grid (36, 4, 32=G*B).  t selects theta/phi/g.
// ---------------------------------------------------------------------------
__global__ __launch_bounds__(256) void k_proj(const float* __restrict__ W,
                                              const float* __restrict__ bias,
                                              const float* __restrict__ feats,
                                              int t)
{
    const int g = blockIdx.z >> 3, b = blockIdx.z & 7;
    const float* Wp = W + (size_t)g * C1n * Cc;
    const float* bp = bias + (size_t)g * C1n;
    const float* Xp = feats + (size_t)b * Cc * Nn;
    float* Cp = g_PROJ + ((size_t)(t * Gg + g) * Bn + b) * C1n * Nn;
    gemm_body(Wp, Xp, bp, Cp, Cc);
}

// ---------------------------------------------------------------------------
// K2: scores + softmax for stage g.  grid (144, 8), 256 threads,
// dynamic smem: th tile (256x16) + score rows (16x2304).
// Each block: 16 query rows, full 2304-key score row kept in smem.
// ---------------------------------------------------------------------------
#define ATTN_SMEM ((256 * 16 + 16 * Nn) * 4)

__global__ __launch_bounds__(256) void k_attn(int g)
{
    extern __shared__ float sm[];
    float* th_s = sm;              // [c*16 + mi]
    float* s_s  = sm + 256 * 16;   // [mi*Nn + n]

    const int t  = threadIdx.x;
    const int m0 = blockIdx.x * 16;
    const int b  = blockIdx.y;
    const float* TH = g_PROJ + ((size_t)(0 * Gg + g) * Bn + b) * C1n * Nn;
    const float* PH = g_PROJ + ((size_t)(1 * Gg + g) * Bn + b) * C1n * Nn;

    // load theta tile: th_s[c][mi] = TH[c, m0+mi]
    for (int i = t; i < 256 * 16; i += 256) {
        int c = i >> 4, mi = i & 15;
        th_s[i] = TH[(size_t)c * Nn + m0 + mi];
    }
    __syncthreads();

    // scores: thread owns one key column per 256-wide chunk
    for (int nb = 0; nb < Nn / 256; nb++) {
        const int n = nb * 256 + t;
        float acc[16] = {};
#pragma unroll 4
        for (int c = 0; c < 256; c++) {
            float ph = PH[(size_t)c * Nn + n];
            float4 t0 = *(const float4*)&th_s[c * 16 + 0];
            float4 t1 = *(const float4*)&th_s[c * 16 + 4];
            float4 t2 = *(const float4*)&th_s[c * 16 + 8];
            float4 t3 = *(const float4*)&th_s[c * 16 + 12];
            acc[0]  += t0.x * ph; acc[1]  += t0.y * ph; acc[2]  += t0.z * ph; acc[3]  += t0.w * ph;
            acc[4]  += t1.x * ph; acc[5]  += t1.y * ph; acc[6]  += t1.z * ph; acc[7]  += t1.w * ph;
            acc[8]  += t2.x * ph; acc[9]  += t2.y * ph; acc[10] += t2.z * ph; acc[11] += t2.w * ph;
            acc[12] += t3.x * ph; acc[13] += t3.y * ph; acc[14] += t3.z * ph; acc[15] += t3.w * ph;
        }
#pragma unroll
        for (int mi = 0; mi < 16; mi++)
            s_s[mi * Nn + n] = acc[mi] * SCALEf;
    }
    __syncthreads();

    // softmax: warp w handles rows w and w+8
    const int w = t >> 5, lane = t & 31;
    for (int mi = w; mi < 16; mi += 8) {
        float* row = s_s + mi * Nn;
        float mx = -1e30f;
        for (int j = lane; j < Nn; j += 32) mx = fmaxf(mx, row[j]);
#pragma unroll
        for (int off = 16; off; off >>= 1) mx = fmaxf(mx, __shfl_xor_sync(0xffffffffu, mx, off));
        float sum = 0.0f;
        for (int j = lane; j < Nn; j += 32) {
            float e = __expf(row[j] - mx);
            row[j] = e;
            sum += e;
        }
#pragma unroll
        for (int off = 16; off; off >>= 1) sum += __shfl_xor_sync(0xffffffffu, sum, off);
        float inv = 1.0f / sum;
        float* Arow = g_A + ((size_t)b * Nn + (m0 + mi)) * Nn;
        for (int j = lane; j < Nn; j += 32) Arow[j] = row[j] * inv;
    }
}

// ---------------------------------------------------------------------------
// K3: Y[c,m] = sum_n GX[c,n] * A[m,n]   (NT GEMM, both K-contiguous)
// grid (36=m, 4=c, 8=b), BK=32
// ---------------------------------------------------------------------------
__global__ __launch_bounds__(256) void k_av(int g)
{
    __shared__ float Gs[32][68];   // [k][c]
    __shared__ float As[32][68];   // [k][m]
    const int t  = threadIdx.x;
    const int m0 = blockIdx.x * 64;
    const int c0 = blockIdx.y * 64;
    const int b  = blockIdx.z;
    const float* GX   = g_PROJ + ((size_t)(2 * Gg + g) * Bn + b) * C2n * Nn;
    const float* Amat = g_A + (size_t)b * Nn * Nn;
    float* Yp = g_Y + ((size_t)g * Bn + b) * C2n * Nn;
    const int tx = t & 15, ty = t >> 4;

    float acc[4][4] = {};
    for (int k0 = 0; k0 < Nn; k0 += 32) {
        float4 gv[2], av[2];
#pragma unroll
        for (int l = 0; l < 2; l++) {
            int lin = t + 256 * l;
            int row = lin >> 3, c4 = lin & 7;
            gv[l] = *(const float4*)&GX[(size_t)(c0 + row) * Nn + k0 + c4 * 4];
            av[l] = *(const float4*)&Amat[(size_t)(m0 + row) * Nn + k0 + c4 * 4];
        }
        __syncthreads();
#pragma unroll
        for (int l = 0; l < 2; l++) {
            int lin = t + 256 * l;
            int row = lin >> 3, c4 = lin & 7;
            Gs[c4 * 4 + 0][row] = gv[l].x; Gs[c4 * 4 + 1][row] = gv[l].y;
            Gs[c4 * 4 + 2][row] = gv[l].z; Gs[c4 * 4 + 3][row] = gv[l].w;
            As[c4 * 4 + 0][row] = av[l].x; As[c4 * 4 + 1][row] = av[l].y;
            As[c4 * 4 + 2][row] = av[l].z; As[c4 * 4 + 3][row] = av[l].w;
        }
        __syncthreads();
#pragma unroll
        for (int kk = 0; kk < 32; kk++) {
            float4 a4 = *(const float4*)&Gs[kk][ty * 4];
            float4 b4 = *(const float4*)&As[kk][tx * 4];
            float a[4] = {a4.x, a4.y, a4.z, a4.w};
            float bb[4] = {b4.x, b4.y, b4.z, b4.w};
#pragma unroll
            for (int j = 0; j < 4; j++)
#pragma unroll
                for (int i = 0; i < 4; i++)
                    acc[j][i] += a[j] * bb[i];
        }
    }
#pragma unroll
    for (int j = 0; j < 4; j++)
#pragma unroll
        for (int i = 0; i < 4; i++)
            Yp[(size_t)(c0 + ty * 4 + j) * Nn + m0 + tx * 4 + i] = acc[j][i];
}

// ---------------------------------------------------------------------------
// K4: W-conv -> PR in final concat channel order. grid (36, 2, 32=G*B)
// ---------------------------------------------------------------------------
__global__ __launch_bounds__(256) void k_wy(const float* __restrict__ w_w,
                                            const float* __restrict__ w_b)
{
    const int g = blockIdx.z >> 3, b = blockIdx.z & 7;
    const float* Wp = w_w + (size_t)g * CGn * C2n;
    const float* bp = w_b + (size_t)g * CGn;
    const float* Xp = g_Y + ((size_t)g * Bn + b) * C2n * Nn;
    float* Cp = g_PR + (size_t)b * 512 * Nn + (size_t)g * CGn * Nn;
    gemm_body(Wp, Xp, bp, Cp, C2n);
}

// ---------------------------------------------------------------------------
// K5/K8: BN statistics over (B, N) per channel. which=0 -> PR/mean1,
// which=1 -> X(d_out)/mean2. grid 512 blocks x 256 threads.
// ---------------------------------------------------------------------------
__global__ void k_bnstats(const float* __restrict__ Xarg, int which)
{
    const float* X = (which == 0) ? g_PR : Xarg;
    float* meanp = (which == 0) ? g_mean1 : g_mean2;
    float* varp  = (which == 0) ? g_var1  : g_var2;
    const int ch = blockIdx.x, t = threadIdx.x;
    double s = 0.0, s2 = 0.0;
    for (int i = t; i < Bn * Nn; i += 256) {
        int b = i / Nn, n = i - b * Nn;
        float v = X[((size_t)b * 512 + ch) * Nn + n];
        s += v; s2 += (double)v * v;
    }
    __shared__ double sh0[256], sh1[256];
    sh0[t] = s; sh1[t] = s2;
    __syncthreads();
    for (int o = 128; o > 0; o >>= 1) {
        if (t < o) { sh0[t] += sh0[t + o]; sh1[t] += sh1[t + o]; }
        __syncthreads();
    }
    if (t == 0) {
        double cnt = (double)Bn * Nn;
        double m = sh0[0] / cnt;
        meanp[ch] = (float)m;
        varp[ch] = (float)(sh1[0] / cnt - m * m);
    }
}

// K6: fold prior-BN into bottleneck weight column scales. 1 block, 1024 thr.
__global__ void k_prep1(const float* __restrict__ wg, const float* __restrict__ wb)
{
    int c = threadIdx.x;
    if (c < 512) {
        float sv = wg[c] * rsqrtf(g_var1[c] + EPSf);
        g_tc[c] = wb[c] - g_mean1[c] * sv;
        g_ws[512 + c] = sv;
    } else {
        g_ws[c - 512] = 1.0f;
    }
}

// K7: folded constant bias: const[o] = bc_b[o] + sum_c bc_w[o,512+c]*t[c]
__global__ void k_prep2(const float* __restrict__ bc_w, const float* __restrict__ bc_b)
{
    int o = blockIdx.x * blockDim.x + threadIdx.x;
    float s = bc_b[o];
    for (int c = 0; c < 512; c++)
        s += bc_w[(size_t)o * 1024 + 512 + c] * g_tc[c];
    g_const[o] = s;
}

// ---------------------------------------------------------------------------
// K9: bottleneck GEMM with dual X source + per-column weight scale + folded
// bias, writing straight to d_out in (b, o, n) layout. grid (36, 8, 8)
// ---------------------------------------------------------------------------
__global__ __launch_bounds__(256) void k_final(const float* __restrict__ bc_w,
                                               const float* __restrict__ feats,
                                               float* __restrict__ out)
{
    __shared__ float Ws[16][68];
    __shared__ float Xs[16][64];
    const int t  = threadIdx.x;
    const int n0 = blockIdx.x * 64;
    const int o0 = blockIdx.y * 64;
    const int b  = blockIdx.z;
    const float* X1 = feats + (size_t)b * Cc * Nn;
    const float* X2 = g_PR  + (size_t)b * 512 * Nn;
    float* Cp = out + (size_t)b * OUTC * Nn;
    const int tx = t & 15, ty = t >> 4;
    const int wrow = t >> 2, wc4 = t & 3;
    const int xrow = t >> 4, xc4 = t & 15;

    float acc[4][4] = {};
    for (int k0 = 0; k0 < 1024; k0 += 16) {
        float4 wv = *(const float4*)&bc_w[(size_t)(o0 + wrow) * 1024 + k0 + wc4 * 4];
        float4 sc = *(const float4*)&g_ws[k0 + wc4 * 4];
        wv.x *= sc.x; wv.y *= sc.y; wv.z *= sc.z; wv.w *= sc.w;
        const float* Xb = (k0 < 512) ? (X1 + (size_t)k0 * Nn) : (X2 + (size_t)(k0 - 512) * Nn);
        float4 xv = *(const float4*)&Xb[(size_t)xrow * Nn + n0 + xc4 * 4];
        __syncthreads();
        Ws[wc4 * 4 + 0][wrow] = wv.x;
        Ws[wc4 * 4 + 1][wrow] = wv.y;
        Ws[wc4 * 4 + 2][wrow] = wv.z;
        Ws[wc4 * 4 + 3][wrow] = wv.w;
        *(float4*)&Xs[xrow][xc4 * 4] = xv;
        __syncthreads();
#pragma unroll
        for (int kk = 0; kk < 16; kk++) {
            float4 a4 = *(const float4*)&Ws[kk][ty * 4];
            float4 b4 = *(const float4*)&Xs[kk][tx * 4];
            float a[4] = {a4.x, a4.y, a4.z, a4.w};
            float bb[4] = {b4.x, b4.y, b4.z, b4.w};
#pragma unroll
            for (int j = 0; j < 4; j++)
#pragma unroll
                for (int i = 0; i < 4; i++)
                    acc[j][i] += a[j] * bb[i];
        }
    }
#pragma unroll
    for (int j = 0; j < 4; j++) {
        float bb = g_const[o0 + ty * 4 + j];
#pragma unroll
        for (int i = 0; i < 4; i++)
            Cp[(size_t)(o0 + ty * 4 + j) * Nn + n0 + tx * 4 + i] = acc[j][i] + bb;
    }
}

// K10: final BN applied in place on d_out
__global__ void k_apply(float* __restrict__ out,
                        const float* __restrict__ gamma,
                        const float* __restrict__ beta)
{
    size_t idx = (size_t)blockIdx.x * blockDim.x + threadIdx.x;
    size_t total = (size_t)Bn * OUTC * Nn;
    if (idx >= total) return;
    int ch = (int)((idx / Nn) % OUTC);
    float v = out[idx];
    out[idx] = (v - g_mean2[ch]) * rsqrtf(g_var2[ch] + EPSf) * gamma[ch] + beta[ch];
}

// ---------------------------------------------------------------------------
// Launch
// ---------------------------------------------------------------------------
extern "C" void kernel_launch(void* const* d_in, const int* in_sizes, int n_in,
                              void* d_out, int out_size)
{
    const float* feats    = (const float*)d_in[0];
    const float* theta_w  = (const float*)d_in[1];
    const float* theta_b  = (const float*)d_in[2];
    const float* phi_w    = (const float*)d_in[3];
    const float* phi_b    = (const float*)d_in[4];
    const float* g_w      = (const float*)d_in[5];
    const float* g_b      = (const float*)d_in[6];
    const float* w_w      = (const float*)d_in[7];
    const float* w_b      = (const float*)d_in[8];
    const float* w_gamma  = (const float*)d_in[9];
    const float* w_beta   = (const float*)d_in[10];
    const float* bc_w     = (const float*)d_in[11];
    const float* bc_b     = (const float*)d_in[12];
    const float* bc_gamma = (const float*)d_in[13];
    const float* bc_beta  = (const float*)d_in[14];
    float* out = (float*)d_out;

    cudaFuncSetAttribute(k_attn, cudaFuncAttributeMaxDynamicSharedMemorySize, ATTN_SMEM);

    dim3 blk(256);
    // projections: theta, phi, g
    k_proj<<<dim3(Nn / 64, C1n / 64, Gg * Bn), blk>>>(theta_w, theta_b, feats, 0);
    k_proj<<<dim3(Nn / 64, C1n / 64, Gg * Bn), blk>>>(phi_w,   phi_b,   feats, 1);
    k_proj<<<dim3(Nn / 64, C1n / 64, Gg * Bn), blk>>>(g_w,     g_b,     feats, 2);

    // per-stage attention (A buffer reused, stream-ordered)
    for (int g = 0; g < Gg; g++) {
        k_attn<<<dim3(Nn / 16, Bn), blk, ATTN_SMEM>>>(g);
        k_av<<<dim3(Nn / 64, C2n / 64, Bn), blk>>>(g);
    }

    // W conv into concat layout
    k_wy<<<dim3(Nn / 64, CGn / 64, Gg * Bn), blk>>>(w_w, w_b);

    // prior BN stats + fold into bottleneck GEMM
    k_bnstats<<<512, 256>>>(nullptr, 0);
    k_prep1<<<1, 1024>>>(w_gamma, w_beta);
    k_prep2<<<2, 256>>>(bc_w, bc_b);

    // bottleneck GEMM straight into d_out
    k_final<<<dim3(Nn / 64, OUTC / 64, Bn), blk>>>(bc_w, feats, out);

    // output BN stats + in-place apply
    k_bnstats<<<512, 256>>>((const float*)out, 1);
    size_t total = (size_t)Bn * OUTC * Nn;
    k_apply<<<(unsigned)((total + 255) / 256), 256>>>(out, bc_gamma, bc_beta);
}

// round 9
// speedup vs baseline: 5.3429x; 5.3429x over previous
#include <cuda_runtime.h>
#include <cuda_bf16.h>
#include <cstdint>
#include <cstddef>

#define Bn 8
#define Cc 512
#define Nn 2304
#define C1n 256
#define Gg 4
#define EPSf 1e-5f
#define CNTf 18432.0f
#define SCALEf 0.0625f

// ---------------- arenas (device globals; allocation-free) ----------------
constexpr size_t SZ_FT = (size_t)Bn*Nn*Cc;
constexpr size_t SZ_P  = (size_t)Gg*Bn*Nn*C1n;
constexpr size_t SZ_AT = (size_t)Bn*Nn*Nn;
constexpr size_t SZ_Y  = (size_t)Bn*Nn*C1n;
constexpr size_t SZ_PR = (size_t)Bn*Nn*512;
constexpr size_t SZ_TW = (size_t)Gg*C1n*Cc;
constexpr size_t SZ_WW = (size_t)Gg*128*C1n;
constexpr size_t SZ_BC = (size_t)512*1024;

constexpr size_t O_FT = 0;
constexpr size_t O_TH = O_FT + 2*SZ_FT;
constexpr size_t O_PH = O_TH + 2*SZ_P;
constexpr size_t O_GX = O_PH + 2*SZ_P;
constexpr size_t O_AT = O_GX + 2*SZ_P;
constexpr size_t O_Y  = O_AT + 2*SZ_AT;
constexpr size_t O_PR = O_Y  + 2*SZ_Y;
constexpr size_t O_TW = O_PR + 2*SZ_PR;
constexpr size_t O_PW = O_TW + 2*SZ_TW;
constexpr size_t O_GW = O_PW + 2*SZ_TW;
constexpr size_t O_WW = O_GW + 2*SZ_TW;
constexpr size_t O_BC = O_WW + 2*SZ_WW;
constexpr size_t BF_TOT = O_BC + 2*SZ_BC;

constexpr size_t F_S  = 0;
constexpr size_t F_OT = F_S + SZ_AT;
constexpr size_t F_S1 = F_OT + SZ_PR;
constexpr size_t F_S2 = F_S1 + 512;
constexpr size_t F_SV = F_S2 + 512;
constexpr size_t F_TC = F_SV + 512;
constexpr size_t F_CB = F_TC + 512;
constexpr size_t F_TOT = F_CB + 512;

__device__ __align__(1024) __nv_bfloat16 g_bf[BF_TOT];
__device__ __align__(1024) float g_fs[F_TOT];

// ---------------- warp-MMA helpers (portable sm_80+ path) ----------------
__device__ __forceinline__ uint32_t smem_to_u32(const void* p) {
    uint32_t a;
    asm("{ .reg .u64 t; cvta.to.shared.u64 t, %1; cvt.u32.u64 %0, t; }" : "=r"(a) : "l"(p));
    return a;
}
__device__ __forceinline__ void ldm4(uint32_t* r, uint32_t addr) {
    asm volatile("ldmatrix.sync.aligned.m8n8.x4.shared.b16 {%0,%1,%2,%3}, [%4];"
        : "=r"(r[0]), "=r"(r[1]), "=r"(r[2]), "=r"(r[3]) : "r"(addr));
}
__device__ __forceinline__ void mma16816(float* d, const uint32_t* a, const uint32_t* b) {
    asm volatile("mma.sync.aligned.m16n8k16.row.col.f32.bf16.bf16.f32 "
        "{%0,%1,%2,%3}, {%4,%5,%6,%7}, {%8,%9}, {%0,%1,%2,%3};"
        : "+f"(d[0]), "+f"(d[1]), "+f"(d[2]), "+f"(d[3])
        : "r"(a[0]), "r"(a[1]), "r"(a[2]), "r"(a[3]), "r"(b[0]), "r"(b[1]));
}
#define CPA16(dst, src) asm volatile("cp.async.cg.shared.global [%0], [%1], 16;" :: "r"(dst), "l"(src))
#define CPA_COMMIT() asm volatile("cp.async.commit_group;" ::: "memory")
#define CPA_WAIT0()  asm volatile("cp.async.wait_group 0;" ::: "memory")

__device__ __forceinline__ int zidx(int sel, int z) {
    return sel == 0 ? z : (sel == 1 ? (z & 7) : (z >> 3));
}

// smem: 4 tiles of 128 rows x 64 bf16 (128B rows, XOR-8 16B-chunk swizzle)
#define T0 0
#define T1 16384
#define T2 32768
#define T3 49152
#define SMEM_BYTES 65536

// async-load one 128x64 bf16 tile into swizzled smem
__device__ __forceinline__ void load_tile(const __nv_bfloat16* __restrict__ g,
                                          long ld, uint32_t sbase, int t) {
#pragma unroll
    for (int i = 0; i < 4; i++) {
        int idx = i * 256 + t, row = idx >> 3, c = idx & 7;
        const void* src = g + (size_t)row * ld + c * 8;
        uint32_t dst = sbase + row * 128 + ((c ^ (row & 7)) * 16);
        CPA16(dst, src);
    }
}

// ---------------------------------------------------------------------------
// Split-bf16 warp-MMA GEMM: C[m,n] = sum_k A[m,k]*B[n,k] (+bias)
// CTA 128x128, 8 warps of 32x64. 3 products per K16: AhBh + AlBh + AhBl.
// EPI: 0 fp32 out (g_fs), 1 split-bf16 out. BIASM: 0 none, 1 col ext,
// 2 row ext, 3 col from g_fs[F_CB].
// ---------------------------------------------------------------------------
template<int EPI, int BIASM>
__global__ __launch_bounds__(256, 2) void k_mma(
    size_t oA, size_t pszA, long sAz, int selA, int lda, size_t oA2, int ksplit,
    size_t oB, size_t pszB, long sBz, int selB, int ldb, int K,
    const float* __restrict__ bias, long sbz, int selBias,
    size_t oC, long sCz, int ldc, size_t pszC)
{
    extern __shared__ char sm[];
    const int t = threadIdx.x, wid = t >> 5, lane = t & 31;
    const int wm = wid & 3, wn = wid >> 2;           // warp grid 4(m) x 2(n)
    const int m0 = blockIdx.x * 128, n0 = blockIdx.y * 128, z = blockIdx.z;
    const uint32_t sb = smem_to_u32(sm);

    const __nv_bfloat16* A  = g_bf + oA  + (size_t)zidx(selA, z) * sAz;
    const __nv_bfloat16* A2 = g_bf + oA2 + (size_t)zidx(selA, z) * sAz;
    const __nv_bfloat16* B  = g_bf + oB  + (size_t)zidx(selB, z) * sBz;

    float acc[2][8][4];
#pragma unroll
    for (int i = 0; i < 2; i++)
#pragma unroll
        for (int j = 0; j < 8; j++)
#pragma unroll
            for (int k = 0; k < 4; k++) acc[i][j][k] = 0.0f;

    // ldmatrix address components (within a tile)
    const int a_row = (lane & 15);             // + wm*32 + mt*16
    const int a_chi = (lane >> 4);             // + ks*2
    const int b_mi  = lane >> 3, b_lm = lane & 7;
    const int b_row = (b_mi >> 1) * 8 + b_lm;  // + wn*64 + ng*16
    const int b_chi = (b_mi & 1);              // + ks*2

    for (int k0 = 0; k0 < K; k0 += 64) {
        __syncthreads();   // previous compute done before overwriting smem
        const __nv_bfloat16* a = (k0 < ksplit)
            ? A  + (size_t)m0 * lda + k0
            : A2 + (size_t)m0 * lda + (k0 - ksplit);
        load_tile(a,        lda, sb + T0, t);
        load_tile(a + pszA, lda, sb + T1, t);
        const __nv_bfloat16* bsrc = B + (size_t)n0 * ldb + k0;
        load_tile(bsrc,        ldb, sb + T2, t);
        load_tile(bsrc + pszB, ldb, sb + T3, t);
        CPA_COMMIT();
        CPA_WAIT0();
        __syncthreads();

#pragma unroll
        for (int ks = 0; ks < 4; ks++) {
            uint32_t ah[2][4], al[2][4], bf[4][4];
#pragma unroll
            for (int mt = 0; mt < 2; mt++) {
                int row = wm * 32 + mt * 16 + a_row;
                int ch  = (ks * 2 + a_chi) ^ (row & 7);
                ldm4(ah[mt], sb + T0 + row * 128 + ch * 16);
                ldm4(al[mt], sb + T1 + row * 128 + ch * 16);
            }
#pragma unroll
            for (int ng = 0; ng < 4; ng++) {   // B hi: 16 n-rows per ldm4
                int row = wn * 64 + ng * 16 + b_row;
                int ch  = (ks * 2 + b_chi) ^ (row & 7);
                ldm4(bf[ng], sb + T2 + row * 128 + ch * 16);
            }
#pragma unroll
            for (int mt = 0; mt < 2; mt++)
#pragma unroll
                for (int nt = 0; nt < 8; nt++)
                    mma16816(acc[mt][nt], ah[mt], &bf[nt >> 1][(nt & 1) * 2]);
#pragma unroll
            for (int mt = 0; mt < 2; mt++)
#pragma unroll
                for (int nt = 0; nt < 8; nt++)
                    mma16816(acc[mt][nt], al[mt], &bf[nt >> 1][(nt & 1) * 2]);
#pragma unroll
            for (int ng = 0; ng < 4; ng++) {   // B lo (overwrite)
                int row = wn * 64 + ng * 16 + b_row;
                int ch  = (ks * 2 + b_chi) ^ (row & 7);
                ldm4(bf[ng], sb + T3 + row * 128 + ch * 16);
            }
#pragma unroll
            for (int mt = 0; mt < 2; mt++)
#pragma unroll
                for (int nt = 0; nt < 8; nt++)
                    mma16816(acc[mt][nt], ah[mt], &bf[nt >> 1][(nt & 1) * 2]);
        }
    }

    // ---------------- epilogue: straight from registers ----------------
    const size_t cbase = oC + (size_t)z * sCz;
    const float* cb  = (BIASM == 3) ? (g_fs + F_CB)
                     : (BIASM == 1) ? (bias + (size_t)zidx(selBias, z) * sbz) : nullptr;
    const float* rb  = (BIASM == 2) ? (bias + (size_t)zidx(selBias, z) * sbz) : nullptr;

#pragma unroll
    for (int mt = 0; mt < 2; mt++) {
        int r1 = m0 + wm * 32 + mt * 16 + (lane >> 2);
        int r2 = r1 + 8;
        float rb1 = 0.0f, rb2 = 0.0f;
        if (BIASM == 2) { rb1 = __ldg(rb + r1); rb2 = __ldg(rb + r2); }
#pragma unroll
        for (int nt = 0; nt < 8; nt++) {
            int cn = n0 + wn * 64 + nt * 8 + (lane & 3) * 2;
            float b0 = 0.0f, b1 = 0.0f;
            if (BIASM == 1 || BIASM == 3) { b0 = cb[cn]; b1 = cb[cn + 1]; }
            float v00 = acc[mt][nt][0] + b0 + rb1;
            float v01 = acc[mt][nt][1] + b1 + rb1;
            float v10 = acc[mt][nt][2] + b0 + rb2;
            float v11 = acc[mt][nt][3] + b1 + rb2;
            size_t i1 = cbase + (size_t)r1 * ldc + cn;
            size_t i2 = cbase + (size_t)r2 * ldc + cn;
            if (EPI == 0) {
                *(float2*)(g_fs + i1) = make_float2(v00, v01);
                *(float2*)(g_fs + i2) = make_float2(v10, v11);
            } else {
                __nv_bfloat16 h00 = __float2bfloat16(v00), h01 = __float2bfloat16(v01);
                __nv_bfloat16 h10 = __float2bfloat16(v10), h11 = __float2bfloat16(v11);
                *(__nv_bfloat162*)(g_bf + i1) = __nv_bfloat162(h00, h01);
                *(__nv_bfloat162*)(g_bf + i2) = __nv_bfloat162(h10, h11);
                *(__nv_bfloat162*)(g_bf + i1 + pszC) = __nv_bfloat162(
                    __float2bfloat16(v00 - __bfloat162float(h00)),
                    __float2bfloat16(v01 - __bfloat162float(h01)));
                *(__nv_bfloat162*)(g_bf + i2 + pszC) = __nv_bfloat162(
                    __float2bfloat16(v10 - __bfloat162float(h10)),
                    __float2bfloat16(v11 - __bfloat162float(h11)));
            }
        }
    }
}

// ---------------- aux kernels ----------------
__global__ void k_split(const float* __restrict__ src, size_t dst, size_t psz, int n)
{
    int i = blockIdx.x * 256 + threadIdx.x;
    if (i >= n) return;
    float v = src[i];
    __nv_bfloat16 h = __float2bfloat16(v);
    g_bf[dst + i] = h;
    g_bf[dst + psz + i] = __float2bfloat16(v - __bfloat162float(h));
}

__global__ void k_trans(const float* __restrict__ feats)
{
    __shared__ float tile[32][33];
    const int n0 = blockIdx.x * 32, c0 = blockIdx.y * 32, b = blockIdx.z;
    const int tx = threadIdx.x, ty = threadIdx.y;
#pragma unroll
    for (int j = 0; j < 4; j++)
        tile[ty + 8 * j][tx] = feats[((size_t)b * Cc + c0 + ty + 8 * j) * Nn + n0 + tx];
    __syncthreads();
#pragma unroll
    for (int j = 0; j < 4; j++) {
        float v = tile[tx][ty + 8 * j];
        size_t idx = ((size_t)b * Nn + n0 + ty + 8 * j) * Cc + c0 + tx;
        __nv_bfloat16 h = __float2bfloat16(v);
        g_bf[O_FT + idx] = h;
        g_bf[O_FT + SZ_FT + idx] = __float2bfloat16(v - __bfloat162float(h));
    }
}

__global__ __launch_bounds__(256) void k_softmax()
{
    const int m = blockIdx.x, b = blockIdx.y, t = threadIdx.x;
    const size_t base = ((size_t)b * Nn + m) * Nn;
    const float* row = g_fs + F_S + base;
    __shared__ float red[8];
    float v[9], mx = -1e30f;
#pragma unroll
    for (int i = 0; i < 9; i++) { v[i] = row[i * 256 + t] * SCALEf; mx = fmaxf(mx, v[i]); }
#pragma unroll
    for (int o = 16; o; o >>= 1) mx = fmaxf(mx, __shfl_xor_sync(~0u, mx, o));
    if ((t & 31) == 0) red[t >> 5] = mx;
    __syncthreads();
    mx = fmaxf(fmaxf(fmaxf(red[0], red[1]), fmaxf(red[2], red[3])),
               fmaxf(fmaxf(red[4], red[5]), fmaxf(red[6], red[7])));
    __syncthreads();
    float s = 0.0f;
#pragma unroll
    for (int i = 0; i < 9; i++) { v[i] = __expf(v[i] - mx); s += v[i]; }
#pragma unroll
    for (int o = 16; o; o >>= 1) s += __shfl_xor_sync(~0u, s, o);
    if ((t & 31) == 0) red[t >> 5] = s;
    __syncthreads();
    s = red[0] + red[1] + red[2] + red[3] + red[4] + red[5] + red[6] + red[7];
    float inv = 1.0f / s;
#pragma unroll
    for (int i = 0; i < 9; i++) {
        float a = v[i] * inv;
        __nv_bfloat16 h = __float2bfloat16(a);
        g_bf[O_AT + base + i * 256 + t] = h;
        g_bf[O_AT + SZ_AT + base + i * 256 + t] = __float2bfloat16(a - __bfloat162float(h));
    }
}

__global__ void k_zero() { if (threadIdx.x < 1024) g_fs[F_S1 + threadIdx.x] = 0.0f; }

__global__ __launch_bounds__(256) void k_stats(size_t off, size_t psz, int fp)
{
    const int t = threadIdx.x, r0 = blockIdx.x * 128;
    float s1a = 0, s2a = 0, s1b = 0, s2b = 0;
    for (int i = 0; i < 128; i++) {
        size_t base = (size_t)(r0 + i) * 512;
        float x, y;
        if (fp) { x = g_fs[off + base + t]; y = g_fs[off + base + t + 256]; }
        else {
            x = __bfloat162float(g_bf[off + base + t]) + __bfloat162float(g_bf[off + psz + base + t]);
            y = __bfloat162float(g_bf[off + base + t + 256]) + __bfloat162float(g_bf[off + psz + base + t + 256]);
        }
        s1a += x; s2a += x * x; s1b += y; s2b += y * y;
    }
    atomicAdd(&g_fs[F_S1 + t], s1a);       atomicAdd(&g_fs[F_S2 + t], s2a);
    atomicAdd(&g_fs[F_S1 + t + 256], s1b); atomicAdd(&g_fs[F_S2 + t + 256], s2b);
}

__global__ void k_prep(const float* __restrict__ wg, const float* __restrict__ wb)
{
    int c = threadIdx.x;
    float m = g_fs[F_S1 + c] / CNTf, v = g_fs[F_S2 + c] / CNTf - m * m;
    float sv = wg[c] * rsqrtf(v + EPSf);
    g_fs[F_SV + c] = sv;
    g_fs[F_TC + c] = wb[c] - m * sv;
}

__global__ void k_const(const float* __restrict__ bc_w, const float* __restrict__ bc_b)
{
    int o = threadIdx.x;
    float s = bc_b[o];
    for (int c = 0; c < 512; c++) s += bc_w[(size_t)o * 1024 + 512 + c] * g_fs[F_TC + c];
    g_fs[F_CB + o] = s;
}

__global__ void k_foldsplit(const float* __restrict__ bc_w)
{
    size_t i = (size_t)blockIdx.x * 512 + threadIdx.x;
    int k = (int)(i & 1023);
    float f = bc_w[i] * (k < 512 ? 1.0f : g_fs[F_SV + k - 512]);
    __nv_bfloat16 h = __float2bfloat16(f);
    g_bf[O_BC + i] = h;
    g_bf[O_BC + SZ_BC + i] = __float2bfloat16(f - __bfloat162float(h));
}

__global__ void k_finalize(float* __restrict__ out, const float* __restrict__ gamma,
                           const float* __restrict__ beta)
{
    __shared__ float tile[32][33];
    const int n0 = blockIdx.x * 32, o0 = blockIdx.y * 32, b = blockIdx.z;
    const int tx = threadIdx.x, ty = threadIdx.y;
#pragma unroll
    for (int j = 0; j < 4; j++)
        tile[ty + 8 * j][tx] = g_fs[F_OT + ((size_t)b * Nn + n0 + ty + 8 * j) * 512 + o0 + tx];
    __syncthreads();
#pragma unroll
    for (int j = 0; j < 4; j++) {
        int o = o0 + ty + 8 * j;
        float m = g_fs[F_S1 + o] / CNTf, va = g_fs[F_S2 + o] / CNTf - m * m;
        out[((size_t)b * 512 + o) * Nn + n0 + tx] =
            (tile[tx][ty + 8 * j] - m) * rsqrtf(va + EPSf) * gamma[o] + beta[o];
    }
}

// ---------------------------------------------------------------------------
extern "C" void kernel_launch(void* const* d_in, const int* in_sizes, int n_in,
                              void* d_out, int out_size)
{
    const float* feats   = (const float*)d_in[0];
    const float* theta_w = (const float*)d_in[1];
    const float* theta_b = (const float*)d_in[2];
    const float* phi_w   = (const float*)d_in[3];
    const float* phi_b   = (const float*)d_in[4];
    const float* g_w     = (const float*)d_in[5];
    const float* g_b     = (const float*)d_in[6];
    const float* w_w     = (const float*)d_in[7];
    const float* w_b     = (const float*)d_in[8];
    const float* w_gamma = (const float*)d_in[9];
    const float* w_beta  = (const float*)d_in[10];
    const float* bc_w    = (const float*)d_in[11];
    const float* bc_b    = (const float*)d_in[12];
    const float* bc_g    = (const float*)d_in[13];
    const float* bc_be   = (const float*)d_in[14];
    float* out = (float*)d_out;

    cudaFuncSetAttribute(k_mma<1,1>, cudaFuncAttributeMaxDynamicSharedMemorySize, SMEM_BYTES);
    cudaFuncSetAttribute(k_mma<1,2>, cudaFuncAttributeMaxDynamicSharedMemorySize, SMEM_BYTES);
    cudaFuncSetAttribute(k_mma<0,0>, cudaFuncAttributeMaxDynamicSharedMemorySize, SMEM_BYTES);
    cudaFuncSetAttribute(k_mma<1,0>, cudaFuncAttributeMaxDynamicSharedMemorySize, SMEM_BYTES);
    cudaFuncSetAttribute(k_mma<0,3>, cudaFuncAttributeMaxDynamicSharedMemorySize, SMEM_BYTES);

    k_split<<<(int)(SZ_TW + 255) / 256, 256>>>(theta_w, O_TW, SZ_TW, (int)SZ_TW);
    k_split<<<(int)(SZ_TW + 255) / 256, 256>>>(phi_w,   O_PW, SZ_TW, (int)SZ_TW);
    k_split<<<(int)(SZ_TW + 255) / 256, 256>>>(g_w,     O_GW, SZ_TW, (int)SZ_TW);
    k_split<<<(int)(SZ_WW + 255) / 256, 256>>>(w_w,     O_WW, SZ_WW, (int)SZ_WW);
    k_trans<<<dim3(Nn / 32, Cc / 32, Bn), dim3(32, 8)>>>(feats);

    const int BIG = 1 << 30;
    // theta: TH[g][b][n][256]
    k_mma<1,1><<<dim3(18, 2, 32), 256, SMEM_BYTES>>>(
        O_FT, SZ_FT, (long)Nn * Cc, 1, Cc, O_FT, BIG,
        O_TW, SZ_TW, (long)C1n * Cc, 2, Cc, Cc,
        theta_b, C1n, 2, O_TH, (long)Nn * C1n, C1n, SZ_P);
    // phi
    k_mma<1,1><<<dim3(18, 2, 32), 256, SMEM_BYTES>>>(
        O_FT, SZ_FT, (long)Nn * Cc, 1, Cc, O_FT, BIG,
        O_PW, SZ_TW, (long)C1n * Cc, 2, Cc, Cc,
        phi_b, C1n, 2, O_PH, (long)Nn * C1n, C1n, SZ_P);
    // g: GX[g][b][c2][n]
    k_mma<1,2><<<dim3(2, 18, 32), 256, SMEM_BYTES>>>(
        O_GW, SZ_TW, (long)C1n * Cc, 2, Cc, O_GW, BIG,
        O_FT, SZ_FT, (long)Nn * Cc, 1, Cc, Cc,
        g_b, C1n, 2, O_GX, (long)C1n * Nn, Nn, SZ_P);

    for (int g = 0; g < Gg; g++) {
        size_t go = (size_t)g * 8 * Nn * C1n;
        // scores -> g_fs[F_S]
        k_mma<0,0><<<dim3(18, 18, 8), 256, SMEM_BYTES>>>(
            O_TH + go, SZ_P, (long)Nn * C1n, 0, C1n, O_TH + go, BIG,
            O_PH + go, SZ_P, (long)Nn * C1n, 0, C1n, C1n,
            nullptr, 0, 0, F_S, (long)Nn * Nn, Nn, 0);
        k_softmax<<<dim3(Nn, Bn), 256>>>();
        // AV -> Y[b][n][256]
        k_mma<1,0><<<dim3(18, 2, 8), 256, SMEM_BYTES>>>(
            O_AT, SZ_AT, (long)Nn * Nn, 0, Nn, O_AT, BIG,
            O_GX + go, SZ_P, (long)C1n * Nn, 0, Nn, Nn,
            nullptr, 0, 0, O_Y, (long)Nn * C1n, C1n, SZ_Y);
        // W conv -> PR[b][n][512] at col g*128
        k_mma<1,1><<<dim3(18, 1, 8), 256, SMEM_BYTES>>>(
            O_Y, SZ_Y, (long)Nn * C1n, 0, C1n, O_Y, BIG,
            O_WW + (size_t)g * 128 * C1n, SZ_WW, 0, 0, C1n, C1n,
            w_b + g * 128, 0, 0, O_PR + (size_t)g * 128, (long)Nn * 512, 512, SZ_PR);
    }

    k_zero<<<1, 1024>>>();
    k_stats<<<144, 256>>>(O_PR, SZ_PR, 0);
    k_prep<<<1, 512>>>(w_gamma, w_beta);
    k_const<<<1, 512>>>(bc_w, bc_b);
    k_foldsplit<<<1024, 512>>>(bc_w);

    // bottleneck -> outT[b][n][512] fp32  (A = [feats^T | PR] split at k=512)
    k_mma<0,3><<<dim3(18, 4, 8), 256, SMEM_BYTES>>>(
        O_FT, SZ_FT, (long)Nn * 512, 0, 512, O_PR, 512,
        O_BC, SZ_BC, 0, 0, 1024, 1024,
        nullptr, 0, 0, F_OT, (long)Nn * 512, 512, 0);

    k_zero<<<1, 1024>>>();
    k_stats<<<144, 256>>>(F_OT, 0, 1);
    k_finalize<<<dim3(Nn / 32, 16, Bn), dim3(32, 8)>>>(out, bc_g, bc_be);
}